// round 6
// baseline (speedup 1.0000x reference)
#include <cuda_runtime.h>
#include <cuda_bf16.h>
#include <stdint.h>

// Inputs (metadata order):
//   d_in[0]: inputs_t  int32  [1, n_source]   (n_source = 17400)
//   d_in[1]: indices   int32  [N_SYN, 2]  -> (post, pre) per row
//   d_in[2]: weights   float32 [N_SYN]
//   d_in[3]: n_post    (scalar; we use out_size instead)
// Output: float32 [1, n_post]

#define THREADS       256
#define CONS_THREADS  224              // warps 0-6 consume
#define SYN_PER_THR   4
#define TILE          (CONS_THREADS * SYN_PER_THR)   // 896 synapses / tile
#define STAGES        4
#define TILE_IDX_B    (TILE * 8)       // 7168
#define TILE_W_B      (TILE * 4)       // 3584
#define TILE_BYTES    (TILE_IDX_B + TILE_W_B)        // 10752

// SMEM layout (static):
//   [0,64)      : 8 mbarriers (full[4] @ 0..31, empty[4] @ 32..63)
//   [64,2240)   : activity bitmask (up to 544 words)
//   [2304, ...) : 4 stages x 10752B  (idx then w per stage)
#define OFF_BITS    64
#define OFF_STAGE0  2304
#define SMEM_TOTAL  (OFF_STAGE0 + STAGES * TILE_BYTES)   // 45312

// Activity bitmask scratch (rebuilt every call -> deterministic).
__device__ uint32_t g_actbits[65536];

// ---------------------------------------------------------------------------
__global__ void __launch_bounds__(256) prep_kernel(
    const int* __restrict__ act, int n_source,
    float* __restrict__ out, int n_out,
    int n_src_padded)
{
    int i = blockIdx.x * blockDim.x + threadIdx.x;
    if (i < n_out) out[i] = 0.0f;
    if (i < n_src_padded) {
        bool active = (i < n_source) && (act[i] > 0);
        unsigned mask = __ballot_sync(0xFFFFFFFFu, active);
        if ((threadIdx.x & 31) == 0) g_actbits[i >> 5] = mask;
    }
}

// ---------------------------------------------------------------------------
// PTX helpers
// ---------------------------------------------------------------------------
__device__ __forceinline__ uint32_t smem_u32(const void* p) {
    uint32_t a;
    asm("{ .reg .u64 t; cvta.to.shared.u64 t, %1; cvt.u32.u64 %0, t; }"
        : "=r"(a) : "l"(p));
    return a;
}

#define MBAR_INIT(addr, cnt) \
    asm volatile("mbarrier.init.shared.b64 [%0], %1;" :: "r"(addr), "r"(cnt) : "memory")

#define MBAR_EXPECT_TX(addr, bytes) \
    asm volatile("mbarrier.arrive.expect_tx.shared.b64 _, [%0], %1;" \
                 :: "r"(addr), "r"(bytes) : "memory")

#define MBAR_ARRIVE(addr) \
    asm volatile("mbarrier.arrive.shared.b64 _, [%0];" :: "r"(addr) : "memory")

#define MBAR_WAIT(addr, parity) do {                                          \
    uint32_t _m = (addr), _p = (parity), _d;                                  \
    asm volatile("{\n\t.reg .pred p;\n\t"                                     \
        "mbarrier.try_wait.parity.acquire.cta.shared::cta.b64 p, [%1], %2;\n\t" \
        "selp.b32 %0, 1, 0, p;\n\t}"                                          \
        : "=r"(_d) : "r"(_m), "r"(_p) : "memory");                            \
    if (!_d) {                                                                \
        asm volatile("{\n\t.reg .pred P1;\n\t"                                \
            "WL_%=:\n\t"                                                      \
            "mbarrier.try_wait.parity.acquire.cta.shared::cta.b64 P1, [%0], %1, 0x989680;\n\t" \
            "@P1 bra.uni WD_%=;\n\t"                                          \
            "bra.uni WL_%=;\n\t"                                              \
            "WD_%=:\n\t}"                                                     \
            :: "r"(_m), "r"(_p) : "memory");                                  \
    }                                                                         \
} while (0)

#define BULK_G2S(dst_smem, src_gmem, bytes, mbar) \
    asm volatile("cp.async.bulk.shared::cta.global.mbarrier::complete_tx::bytes " \
                 "[%0], [%1], %2, [%3];"                                      \
                 :: "r"(dst_smem), "l"(src_gmem), "r"(bytes), "r"(mbar) : "memory")

// ---------------------------------------------------------------------------
// Warp-specialized scatter: warp 7 produces via cp.async.bulk (4-stage ring),
// warps 0-6 consume from smem and issue predicated REDs. No __syncthreads in
// the main loop.
// ---------------------------------------------------------------------------
__global__ void __launch_bounds__(THREADS) scatter_ws_kernel(
    const char* __restrict__ g_idx,
    const char* __restrict__ g_w,
    float*      __restrict__ out,
    int ntiles,
    int n_words)
{
    __shared__ __align__(128) unsigned char smem[SMEM_TOTAL];

    const uint32_t sbase = smem_u32(smem);
    uint32_t* sbits = (uint32_t*)(smem + OFF_BITS);

    // full[s] = sbase + s*8 ; empty[s] = sbase + 32 + s*8
    if (threadIdx.x == 0) {
        #pragma unroll
        for (int s = 0; s < STAGES; s++) {
            MBAR_INIT(sbase + s * 8, 1);                 // full: tx-based
            MBAR_INIT(sbase + 32 + s * 8, CONS_THREADS); // empty: all consumers
        }
    }
    for (int j = threadIdx.x; j < n_words; j += THREADS)
        sbits[j] = g_actbits[j];
    __syncthreads();

    const int tid    = threadIdx.x;
    const int stride = gridDim.x;

    if (tid >= CONS_THREADS) {
        // ---- producer path (single thread of warp 7) ----
        if (tid == CONS_THREADS) {
            int i = 0;
            for (int t = blockIdx.x; t < ntiles; t += stride, i++) {
                const int s = i & (STAGES - 1);
                const uint32_t ph = ((i >> 2) & 1) ^ 1;   // first pass passes free
                MBAR_WAIT(sbase + 32 + s * 8, ph);        // wait stage empty
                const uint32_t full = sbase + s * 8;
                const uint32_t dst  = sbase + OFF_STAGE0 + s * TILE_BYTES;
                MBAR_EXPECT_TX(full, TILE_BYTES);
                BULK_G2S(dst,              g_idx + (size_t)t * TILE_IDX_B, TILE_IDX_B, full);
                BULK_G2S(dst + TILE_IDX_B, g_w   + (size_t)t * TILE_W_B,   TILE_W_B,   full);
            }
        }
        return;
    }

    // ---- consumer path (warps 0-6) ----
    int i = 0;
    for (int t = blockIdx.x; t < ntiles; t += stride, i++) {
        const int s = i & (STAGES - 1);
        const uint32_t ph = (i >> 2) & 1;
        MBAR_WAIT(sbase + s * 8, ph);                     // wait stage full

        const unsigned char* stg = smem + OFF_STAGE0 + s * TILE_BYTES;
        const int2*  ib = (const int2*)stg;
        const float* wb = (const float*)(stg + TILE_IDX_B);

        #pragma unroll
        for (int k = 0; k < SYN_PER_THR; k++) {
            const int e = k * CONS_THREADS + tid;
            int2  p = ib[e];
            float w = wb[e];
            if ((sbits[(unsigned)p.y >> 5] >> ((unsigned)p.y & 31u)) & 1u)
                atomicAdd(out + p.x, w);
        }

        MBAR_ARRIVE(sbase + 32 + s * 8);                  // mark stage empty
    }
}

// ---------------------------------------------------------------------------
__global__ void scatter_tail_kernel(
    const int2* __restrict__ idx2,
    const float* __restrict__ w,
    float*       __restrict__ out,
    int start, int n_syn)
{
    int i = start + blockIdx.x * blockDim.x + threadIdx.x;
    if (i >= n_syn) return;
    int2 p = idx2[i];
    if ((g_actbits[(unsigned)p.y >> 5] >> ((unsigned)p.y & 31u)) & 1u)
        atomicAdd(out + p.x, w[i]);
}

// ---------------------------------------------------------------------------
extern "C" void kernel_launch(void* const* d_in, const int* in_sizes, int n_in,
                              void* d_out, int out_size) {
    const int*   act     = (const int*)d_in[0];
    const char*  indices = (const char*)d_in[1];
    const char*  weights = (const char*)d_in[2];
    float*       out     = (float*)d_out;

    const int n_source = in_sizes[0];
    const int n_syn    = in_sizes[2];

    const int n_src_padded = (n_source + 31) & ~31;
    int n_words = n_src_padded >> 5;
    if (n_words > 544) n_words = 544;   // smem bitmask capacity (17408 sources)

    // Prep: zero output + build bitmask.
    {
        int span    = out_size > n_src_padded ? out_size : n_src_padded;
        int threads = 256;
        int blocks  = (span + threads - 1) / threads;
        prep_kernel<<<blocks, threads>>>(act, n_source, out, out_size, n_src_padded);
    }

    const int ntiles = n_syn / TILE;
    if (ntiles > 0) {
        int blocks = 4 * 148;                 // 4 CTAs/SM (45.3KB smem each)
        if (blocks > ntiles) blocks = ntiles;
        scatter_ws_kernel<<<blocks, THREADS>>>(indices, weights, out, ntiles, n_words);
    }

    const int done = ntiles * TILE;
    if (done < n_syn) {
        int rem = n_syn - done;
        int threads = 256;
        int blocks  = (rem + threads - 1) / threads;
        scatter_tail_kernel<<<blocks, threads>>>(
            (const int2*)indices, (const float*)weights, out, done, n_syn);
    }
}

// round 7
// speedup vs baseline: 1.2184x; 1.2184x over previous
#include <cuda_runtime.h>
#include <cuda_bf16.h>
#include <stdint.h>

// Inputs (metadata order):
//   d_in[0]: inputs_t  int32  [1, n_source]   (n_source = 17400)
//   d_in[1]: indices   int32  [N_SYN, 2]  -> (post, pre) per row
//   d_in[2]: weights   float32 [N_SYN]
//   d_in[3]: n_post    (scalar; we use out_size instead)
// Output: float32 [1, n_post]
//
// Model (round 6): duration is pinned by the L2/LTS op wall:
//   11.25M stream-read sectors + 15M RED.ADD.F32 ops ~= 200K LTS-limited
//   cycles ~= 109us. All load-path reorganizations (TMA staging, warp
//   specialization, smem bitmask) measured identical or worse. So: keep the
//   minimal scatter kernel and strip every microsecond of fixed overhead.

// 4 synapses per thread: two int4 index loads + one float4 weight load.
// Activity loads hoisted ahead of the REDs; atomics predicated (~50% skipped).
__global__ void __launch_bounds__(256) scatter4_kernel(
    const int*    __restrict__ act,    // inputs_t, n_source ints (L1/L2-resident)
    const int4*   __restrict__ idx4,   // (post0,pre0,post1,pre1) pairs
    const float4* __restrict__ w4,
    float*        __restrict__ out,
    int n_quads)                        // n_syn / 4
{
    int i = blockIdx.x * blockDim.x + threadIdx.x;
    if (i >= n_quads) return;

    int4   a  = idx4[2 * i];
    int4   b  = idx4[2 * i + 1];
    float4 wv = w4[i];

    // Front-batch the gather loads so all four are in flight before any RED.
    int act0 = __ldg(act + a.y);
    int act1 = __ldg(act + a.w);
    int act2 = __ldg(act + b.y);
    int act3 = __ldg(act + b.w);

    if (act0 > 0) atomicAdd(out + a.x, wv.x);
    if (act1 > 0) atomicAdd(out + a.z, wv.y);
    if (act2 > 0) atomicAdd(out + b.x, wv.z);
    if (act3 > 0) atomicAdd(out + b.z, wv.w);
}

// Tail for n_syn not divisible by 4 (not launched for N_SYN=30M).
__global__ void scatter_tail_kernel(
    const int*  __restrict__ act,
    const int2* __restrict__ idx2,
    const float* __restrict__ w,
    float*       __restrict__ out,
    int start, int n_syn)
{
    int i = start + blockIdx.x * blockDim.x + threadIdx.x;
    if (i >= n_syn) return;
    int2 p = idx2[i];
    if (__ldg(act + p.y) > 0) atomicAdd(out + p.x, w[i]);
}

extern "C" void kernel_launch(void* const* d_in, const int* in_sizes, int n_in,
                              void* d_out, int out_size) {
    const int*   act     = (const int*)d_in[0];
    const int*   indices = (const int*)d_in[1];
    const float* weights = (const float*)d_in[2];
    float*       out     = (float*)d_out;

    const int n_syn = in_sizes[2];   // weights element count

    // Zero the output with a memset node (graph-capturable, no SM launch).
    cudaMemsetAsync(out, 0, (size_t)out_size * sizeof(float), 0);

    const int n_quads = n_syn / 4;
    if (n_quads > 0) {
        int threads = 256;
        int blocks  = (n_quads + threads - 1) / threads;
        scatter4_kernel<<<blocks, threads>>>(
            act, (const int4*)indices, (const float4*)weights, out, n_quads);
    }

    const int done = n_quads * 4;
    if (done < n_syn) {           // not taken for n_syn = 30M
        int rem = n_syn - done;
        int threads = 256;
        int blocks  = (rem + threads - 1) / threads;
        scatter_tail_kernel<<<blocks, threads>>>(
            act, (const int2*)indices, weights, out, done, n_syn);
    }
}